// round 1
// baseline (speedup 1.0000x reference)
#include <cuda_runtime.h>
#include <cstdint>

#define N_NODES 50000
#define N_EDGES 800000
// feature dims: x=64, edge_attr=64, hidden=64, out=64, concat input = 128

// ---------------- scratch (static device allocation — no cudaMalloc) ----------
__device__ float g_summed[N_NODES * 64];
__device__ float g_counts[N_NODES];

// ---------------- packed f32x2 helpers ----------------------------------------
__device__ __forceinline__ unsigned long long pk2(float lo, float hi) {
    unsigned long long r;
    asm("mov.b64 %0, {%1, %2};" : "=l"(r) : "f"(lo), "f"(hi));
    return r;
}
__device__ __forceinline__ float2 up2(unsigned long long v) {
    float2 r;
    asm("mov.b64 {%0, %1}, %2;" : "=f"(r.x), "=f"(r.y) : "l"(v));
    return r;
}
__device__ __forceinline__ void fma2(unsigned long long& d, unsigned long long a,
                                     unsigned long long b) {
    asm("fma.rn.f32x2 %0, %1, %2, %0;" : "+l"(d) : "l"(a), "l"(b));
}
__device__ __forceinline__ void red4(float* addr, float4 v) {
    asm volatile("red.global.add.v4.f32 [%0], {%1, %2, %3, %4};"
                 :: "l"(addr), "f"(v.x), "f"(v.y), "f"(v.z), "f"(v.w)
                 : "memory");
}

// ---------------- zero scratch -------------------------------------------------
__global__ void zero_scratch_kernel() {
    int stride = gridDim.x * blockDim.x;
    int i = blockIdx.x * blockDim.x + threadIdx.x;
    for (int j = i; j < N_NODES * 64; j += stride) g_summed[j] = 0.0f;
    for (int j = i; j < N_NODES; j += stride) g_counts[j] = 0.0f;
}

// ---------------- tiled GEMM core ----------------------------------------------
// Warp tile: 16 rows x 64 outputs. lane: er = lane>>3 (row group), oc = lane&7.
// Lane owns rows {er, er+4, er+8, er+12} (+warp base) and output cols
// {4oc..4oc+3} and {32+4oc..32+4oc+3} as 4 packed-f32x2 pairs per row.
// A reads: 4 broadcast LDS.32 (padded stride -> conflict-free banks)
// B reads: 2 LDS.128 (float4-aligned, 8 distinct banks -> conflict-free)
template <int K, int LDA>
__device__ __forceinline__ void gemm_tile(const float* __restrict__ A0,
                                          const float* __restrict__ Bp,
                                          unsigned long long acc[4][4]) {
    const float* A1 = A0 + 4 * LDA;
    const float* A2 = A0 + 8 * LDA;
    const float* A3 = A0 + 12 * LDA;
#pragma unroll 4
    for (int k = 0; k < K; ++k) {
        ulonglong2 b01 = *reinterpret_cast<const ulonglong2*>(Bp + k * 64);
        ulonglong2 b23 = *reinterpret_cast<const ulonglong2*>(Bp + k * 64 + 32);
        unsigned long long A;
        A = pk2(A0[k], A0[k]);
        fma2(acc[0][0], A, b01.x); fma2(acc[0][1], A, b01.y);
        fma2(acc[0][2], A, b23.x); fma2(acc[0][3], A, b23.y);
        A = pk2(A1[k], A1[k]);
        fma2(acc[1][0], A, b01.x); fma2(acc[1][1], A, b01.y);
        fma2(acc[1][2], A, b23.x); fma2(acc[1][3], A, b23.y);
        A = pk2(A2[k], A2[k]);
        fma2(acc[2][0], A, b01.x); fma2(acc[2][1], A, b01.y);
        fma2(acc[2][2], A, b23.x); fma2(acc[2][3], A, b23.y);
        A = pk2(A3[k], A3[k]);
        fma2(acc[3][0], A, b01.x); fma2(acc[3][1], A, b01.y);
        fma2(acc[3][2], A, b23.x); fma2(acc[3][3], A, b23.y);
    }
}

// ---------------- fused MLP kernel (edge pass / node pass) ---------------------
// TILE = 96 rows per block iteration, 6 warps (16 rows each), 192 threads.
// smem: W_a 128x64 (32KB) + W_b 64x64 (16KB) + biases + input tile 96x132 (~50KB)
//       + 96 row + 96 col ids. ~101KB -> 2 blocks/SM.
#define TILE_R 96
#define S_IN   132   // input tile row stride (floats); %8==4 kills A-load conflicts
#define S_HID  68    // hidden tile row stride (overlaid on input tile)

#define SMEM_FLOATS (8192 + 4096 + 64 + 64 + TILE_R * S_IN)
#define SMEM_BYTES  (SMEM_FLOATS * 4 + TILE_R * 2 * 4)

template <bool EDGE>
__global__ void __launch_bounds__(192, 2)
mlp_kernel(const float* __restrict__ x,
           const void* __restrict__ ei,    // edge_index (int32 or int64), edge pass only
           const float* __restrict__ ea,   // edge_attr, edge pass only
           const float* __restrict__ Wa, const float* __restrict__ ba,
           const float* __restrict__ Wb, const float* __restrict__ bb,
           float* __restrict__ outp)       // node pass only
{
    extern __shared__ float sm[];
    float* sWa = sm;               // 8192
    float* sWb = sWa + 8192;       // 4096
    float* sBa = sWb + 4096;       // 64
    float* sBb = sBa + 64;         // 64
    float* sIn = sBb + 64;         // TILE_R * S_IN
    int*   sRow = reinterpret_cast<int*>(sIn + TILE_R * S_IN);  // 96
    int*   sCol = sRow + TILE_R;                                 // 96

    const int tid  = threadIdx.x;
    const int wid  = tid >> 5;
    const int lane = tid & 31;
    const int er   = lane >> 3;
    const int oc   = lane & 7;
    const int w16  = wid * 16;

    // ---- load weights + biases once per block ----
    {
        const float4* srcA = reinterpret_cast<const float4*>(Wa);  // 2048 float4
        const float4* srcB = reinterpret_cast<const float4*>(Wb);  // 1024 float4
        float4* dA = reinterpret_cast<float4*>(sWa);
        float4* dB = reinterpret_cast<float4*>(sWb);
        for (int i = tid; i < 2048; i += 192) dA[i] = srcA[i];
        for (int i = tid; i < 1024; i += 192) dB[i] = srcB[i];
        if (tid < 64) { sBa[tid] = ba[tid]; sBb[tid] = bb[tid]; }
    }
    __syncthreads();

    // per-lane bias registers for the 8 owned output columns
    const float4 rba0 = reinterpret_cast<const float4*>(sBa)[oc];
    const float4 rba1 = reinterpret_cast<const float4*>(sBa)[8 + oc];
    const float4 rbb0 = reinterpret_cast<const float4*>(sBb)[oc];
    const float4 rbb1 = reinterpret_cast<const float4*>(sBb)[8 + oc];

    const int total  = EDGE ? N_EDGES : N_NODES;
    const int ntiles = (total + TILE_R - 1) / TILE_R;

    for (int tile = blockIdx.x; tile < ntiles; tile += gridDim.x) {
        const int base = tile * TILE_R;
        __syncthreads();  // previous iteration's smem reads complete

        // ---- stage indices (edge pass) + degree counts ----
        if (EDGE) {
            if (tid < TILE_R) {
                const int ge = base + tid;
                int r = 0, c = 0;
                if (ge < N_EDGES) {
                    // dtype sniff: JAX without x64 silently downcasts int64->int32.
                    // If int64, the upper 32-bit words of small nonneg values are 0.
                    const int* e32 = reinterpret_cast<const int*>(ei);
                    const bool is64 = ((e32[1] | e32[3] | e32[5] | e32[7]) == 0);
                    if (is64) {
                        const long long* e64 = reinterpret_cast<const long long*>(ei);
                        r = (int)e64[ge];
                        c = (int)e64[N_EDGES + ge];
                    } else {
                        r = e32[ge];
                        c = e32[N_EDGES + ge];
                    }
                    atomicAdd(&g_counts[r], 1.0f);
                }
                sRow[tid] = r;
                sCol[tid] = c;
            }
            __syncthreads();
        }

        // ---- gather input tile: warp w loads rows [w16, w16+16) ----
        {
            const int half = lane >> 4;  // 0: x half, 1: edge_attr / agg half
            const int q    = lane & 15;
            for (int e16 = 0; e16 < 16; ++e16) {
                const int le = w16 + e16;
                const int gi = base + le;
                float4 v;
                if (EDGE) {
                    const int gsafe = gi < N_EDGES ? gi : N_EDGES - 1;
                    if (half == 0) {
                        const int c = sCol[le];
                        v = reinterpret_cast<const float4*>(x)[c * 16 + q];
                    } else {
                        v = reinterpret_cast<const float4*>(ea)[gsafe * 16 + q];
                    }
                } else {
                    const int n = gi < N_NODES ? gi : N_NODES - 1;
                    if (half == 0) {
                        v = reinterpret_cast<const float4*>(x)[n * 16 + q];
                    } else {
                        const float cnt = g_counts[n];
                        const float s = 1.0f / fmaxf(cnt, 1.0f);
                        v = reinterpret_cast<const float4*>(g_summed)[n * 16 + q];
                        v.x *= s; v.y *= s; v.z *= s; v.w *= s;
                    }
                }
                reinterpret_cast<float4*>(sIn)[le * (S_IN / 4) + lane] = v;
            }
        }
        __syncthreads();

        // ---- GEMM1: [96 x 128] @ [128 x 64] ----
        unsigned long long acc[4][4];
#pragma unroll
        for (int j = 0; j < 4; ++j)
#pragma unroll
            for (int p = 0; p < 4; ++p) acc[j][p] = 0ULL;

        gemm_tile<128, S_IN>(sIn + (w16 + er) * S_IN, sWa + 4 * oc, acc);
        __syncthreads();  // all warps done reading sIn before hidden overlay

        // ---- epilogue 1: relu(acc + ba) -> hidden tile (overlaid, stride 68) ----
        float* sHid = sIn;
#pragma unroll
        for (int j = 0; j < 4; ++j) {
            const int le = w16 + er + 4 * j;
            float2 v0 = up2(acc[j][0]), v1 = up2(acc[j][1]);
            float2 v2 = up2(acc[j][2]), v3 = up2(acc[j][3]);
            float4 o0 = make_float4(fmaxf(v0.x + rba0.x, 0.0f),
                                    fmaxf(v0.y + rba0.y, 0.0f),
                                    fmaxf(v1.x + rba0.z, 0.0f),
                                    fmaxf(v1.y + rba0.w, 0.0f));
            float4 o1 = make_float4(fmaxf(v2.x + rba1.x, 0.0f),
                                    fmaxf(v2.y + rba1.y, 0.0f),
                                    fmaxf(v3.x + rba1.z, 0.0f),
                                    fmaxf(v3.y + rba1.w, 0.0f));
            reinterpret_cast<float4*>(sHid)[le * (S_HID / 4) + oc]     = o0;
            reinterpret_cast<float4*>(sHid)[le * (S_HID / 4) + 8 + oc] = o1;
        }
        __syncthreads();

        // ---- GEMM2: [96 x 64] @ [64 x 64] ----
#pragma unroll
        for (int j = 0; j < 4; ++j)
#pragma unroll
            for (int p = 0; p < 4; ++p) acc[j][p] = 0ULL;

        gemm_tile<64, S_HID>(sHid + (w16 + er) * S_HID, sWb + 4 * oc, acc);

        // ---- epilogue 2: acc + bb -> scatter (edge) / store (node) ----
#pragma unroll
        for (int j = 0; j < 4; ++j) {
            const int le = w16 + er + 4 * j;
            const int gi = base + le;
            float2 v0 = up2(acc[j][0]), v1 = up2(acc[j][1]);
            float2 v2 = up2(acc[j][2]), v3 = up2(acc[j][3]);
            float4 o0 = make_float4(v0.x + rbb0.x, v0.y + rbb0.y,
                                    v1.x + rbb0.z, v1.y + rbb0.w);
            float4 o1 = make_float4(v2.x + rbb1.x, v2.y + rbb1.y,
                                    v3.x + rbb1.z, v3.y + rbb1.w);
            if (EDGE) {
                if (gi < N_EDGES) {
                    float* dst = g_summed + (long long)sRow[le] * 64;
                    red4(dst + 4 * oc, o0);
                    red4(dst + 32 + 4 * oc, o1);
                }
            } else {
                if (gi < N_NODES) {
                    reinterpret_cast<float4*>(outp)[gi * 16 + oc]     = o0;
                    reinterpret_cast<float4*>(outp)[gi * 16 + 8 + oc] = o1;
                }
            }
        }
    }
}

// ---------------- launch --------------------------------------------------------
extern "C" void kernel_launch(void* const* d_in, const int* in_sizes, int n_in,
                              void* d_out, int out_size) {
    const float* x   = reinterpret_cast<const float*>(d_in[0]);
    const void*  ei  = d_in[1];                                   // edge_index
    const float* ea  = reinterpret_cast<const float*>(d_in[2]);   // edge_attr
    // d_in[3] = u (unused), d_in[4] = batch (unused)
    const float* W1a = reinterpret_cast<const float*>(d_in[5]);
    const float* b1a = reinterpret_cast<const float*>(d_in[6]);
    const float* W1b = reinterpret_cast<const float*>(d_in[7]);
    const float* b1b = reinterpret_cast<const float*>(d_in[8]);
    const float* W2a = reinterpret_cast<const float*>(d_in[9]);
    const float* b2a = reinterpret_cast<const float*>(d_in[10]);
    const float* W2b = reinterpret_cast<const float*>(d_in[11]);
    const float* b2b = reinterpret_cast<const float*>(d_in[12]);
    float* out = reinterpret_cast<float*>(d_out);

    cudaFuncSetAttribute(mlp_kernel<true>,
                         cudaFuncAttributeMaxDynamicSharedMemorySize, SMEM_BYTES);
    cudaFuncSetAttribute(mlp_kernel<false>,
                         cudaFuncAttributeMaxDynamicSharedMemorySize, SMEM_BYTES);

    zero_scratch_kernel<<<512, 256>>>();

    // edge pass: message MLP + scatter-sum + degree counts
    mlp_kernel<true><<<304, 192, SMEM_BYTES>>>(x, ei, ea, W1a, b1a, W1b, b1b, nullptr);

    // node pass: [x || agg] MLP -> out
    mlp_kernel<false><<<304, 192, SMEM_BYTES>>>(x, nullptr, nullptr,
                                                W2a, b2a, W2b, b2b, out);
}